// round 12
// baseline (speedup 1.0000x reference)
#include <cuda_runtime.h>
#include <math.h>
#include <stdint.h>

#define B_ 2
#define T_ 2048
#define C_ 1024
#define H_ 16
#define HS_ 64
#define NQKV 1152  // 1024 q + 64 k + 64 v

// Scratch (allocation-free rule: __device__ globals)
__device__ float g_qkv[B_ * T_ * NQKV];    // fused projection output (k/v cols pre-tf32)
__device__ float g_y[B_ * T_ * C_];

__device__ __forceinline__ uint32_t f2tf(float f) {
    uint32_t u;
    asm("cvt.rna.tf32.f32 %0, %1;" : "=r"(u) : "f"(f));
    return u;
}

__device__ __forceinline__ uint32_t smaddr(const void* p) {
    return (uint32_t)__cvta_generic_to_shared(p);
}

__device__ __forceinline__ void cp16(uint32_t s, const void* g) {
    asm volatile("cp.async.cg.shared.global [%0], [%1], 16;" :: "r"(s), "l"(g));
}

__device__ __forceinline__ void mma_tf32(float c[4], const uint32_t* a, const uint32_t* b) {
    asm volatile(
        "mma.sync.aligned.m16n8k8.row.col.f32.tf32.tf32.f32 "
        "{%0,%1,%2,%3}, {%4,%5,%6,%7}, {%8,%9}, {%0,%1,%2,%3};"
        : "+f"(c[0]), "+f"(c[1]), "+f"(c[2]), "+f"(c[3])
        : "r"(a[0]), "r"(a[1]), "r"(a[2]), "r"(a[3]), "r"(b[0]), "r"(b[1]));
}

// C[m,n] = sum_k A[m,k] * W[n,k] (+bias), tf32 tensor cores.
// BM=128, BK=32, BN=128. 256 threads = 8 warps (4m x 2n).
// Double-buffered smem (dynamic, 73728B), register prefetch, ONE barrier per K-iter.
// QKV=true: W = virtual concat Wq(1024)‖Wk(64)‖Wv(64); k/v output cols stored as tf32 bits.
template <bool BIAS, bool QKV>
__global__ __launch_bounds__(256) void gemm_tc(const float* __restrict__ A,
                                               const float* __restrict__ Wq,
                                               const float* __restrict__ Wk,
                                               const float* __restrict__ Wv,
                                               const float* __restrict__ bias,
                                               float* __restrict__ C,
                                               int N, int K) {
    extern __shared__ __align__(16) uint32_t smp[];
    const int ASZ = 128 * 36;  // As0 | As1 | Bs0 | Bs1
    int tid = threadIdx.x, lane = tid & 31, warp = tid >> 5;
    int g = lane >> 2, q4 = lane & 3;
    int wm = warp & 3, wn = warp >> 2;
    int bm = blockIdx.y * 128, bn = blockIdx.x * 128;
    int lr = tid >> 3, lc4 = (tid & 7) * 4;

    float acc[2][8][4];
#pragma unroll
    for (int mt = 0; mt < 2; mt++)
#pragma unroll
        for (int j = 0; j < 8; j++)
#pragma unroll
            for (int e = 0; e < 4; e++) acc[mt][j][e] = 0.f;

    const float* arow[4];
    const float* wrow[4];
#pragma unroll
    for (int t = 0; t < 4; t++) {
        int ra = bm + lr + 32 * t;
        arow[t] = A + (size_t)ra * K + lc4;
        int rw = bn + lr + 32 * t;
        if (QKV)
            wrow[t] = (rw < 1024 ? Wq + (size_t)rw * K
                     : rw < 1088 ? Wk + (size_t)(rw - 1024) * K
                                 : Wv + (size_t)(rw - 1088) * K) + lc4;
        else
            wrow[t] = Wq + (size_t)rw * K + lc4;
    }

    float4 pa[4], pb[4];
#pragma unroll
    for (int t = 0; t < 4; t++) {
        pa[t] = *(const float4*)(arow[t]);
        pb[t] = *(const float4*)(wrow[t]);
    }
#pragma unroll
    for (int t = 0; t < 4; t++) {
        *(uint4*)&smp[(lr + t * 32) * 36 + lc4] =
            make_uint4(f2tf(pa[t].x), f2tf(pa[t].y), f2tf(pa[t].z), f2tf(pa[t].w));
        *(uint4*)&smp[2 * ASZ + (lr + t * 32) * 36 + lc4] =
            make_uint4(f2tf(pb[t].x), f2tf(pb[t].y), f2tf(pb[t].z), f2tf(pb[t].w));
    }
    __syncthreads();

    for (int k0 = 0; k0 < K; k0 += 32) {
        int cur = (k0 >> 5) & 1;
        bool more = (k0 + 32) < K;
        if (more) {
#pragma unroll
            for (int t = 0; t < 4; t++) {
                pa[t] = *(const float4*)(arow[t] + k0 + 32);
                pb[t] = *(const float4*)(wrow[t] + k0 + 32);
            }
        }
        const uint32_t* Asb = smp + cur * ASZ;
        const uint32_t* Bsb = smp + 2 * ASZ + cur * ASZ;
#pragma unroll
        for (int kk = 0; kk < 4; kk++) {
            uint32_t af[2][4], bf[8][2];
#pragma unroll
            for (int mt = 0; mt < 2; mt++) {
                int rb = wm * 32 + mt * 16;
                af[mt][0] = Asb[(rb + g) * 36 + kk * 8 + q4];
                af[mt][1] = Asb[(rb + g + 8) * 36 + kk * 8 + q4];
                af[mt][2] = Asb[(rb + g) * 36 + kk * 8 + q4 + 4];
                af[mt][3] = Asb[(rb + g + 8) * 36 + kk * 8 + q4 + 4];
            }
#pragma unroll
            for (int j = 0; j < 8; j++) {
                int nb = wn * 64 + j * 8 + g;
                bf[j][0] = Bsb[nb * 36 + kk * 8 + q4];
                bf[j][1] = Bsb[nb * 36 + kk * 8 + q4 + 4];
            }
#pragma unroll
            for (int mt = 0; mt < 2; mt++)
#pragma unroll
                for (int j = 0; j < 8; j++) mma_tf32(acc[mt][j], af[mt], bf[j]);
        }
        if (more) {
            uint32_t* Asn = smp + (1 - cur) * ASZ;
            uint32_t* Bsn = smp + 2 * ASZ + (1 - cur) * ASZ;
#pragma unroll
            for (int t = 0; t < 4; t++) {
                *(uint4*)&Asn[(lr + t * 32) * 36 + lc4] =
                    make_uint4(f2tf(pa[t].x), f2tf(pa[t].y), f2tf(pa[t].z), f2tf(pa[t].w));
                *(uint4*)&Bsn[(lr + t * 32) * 36 + lc4] =
                    make_uint4(f2tf(pb[t].x), f2tf(pb[t].y), f2tf(pb[t].z), f2tf(pb[t].w));
            }
            __syncthreads();
        }
    }

#pragma unroll
    for (int mt = 0; mt < 2; mt++)
#pragma unroll
        for (int j = 0; j < 8; j++) {
            int row = bm + wm * 32 + mt * 16 + g;
            int col = bn + wn * 64 + j * 8 + 2 * q4;
            float2 v0 = make_float2(acc[mt][j][0], acc[mt][j][1]);
            float2 v1 = make_float2(acc[mt][j][2], acc[mt][j][3]);
            if (BIAS) {
                float b0 = bias[col], b1 = bias[col + 1];
                v0.x += b0; v0.y += b1; v1.x += b0; v1.y += b1;
            }
            if (QKV && col >= 1024) {  // k/v region: store tf32 bits (pre-converted for attn)
                v0.x = __uint_as_float(f2tf(v0.x));
                v0.y = __uint_as_float(f2tf(v0.y));
                v1.x = __uint_as_float(f2tf(v1.x));
                v1.y = __uint_as_float(f2tf(v1.y));
            }
            *(float2*)&C[(size_t)row * N + col] = v0;
            *(float2*)&C[(size_t)(row + 8) * N + col] = v1;
        }
}

// Flash-style causal MQA attention, tf32 tensor cores.
// 256 thr = 8 warps; each warp owns 16 query rows. 64-key tiles from fused qkv buffer.
// K/V arrive pre-converted to tf32 bits; 3-stage cp.async pipeline, ONE barrier per tile.
// q remap quirk: q[b,h,t,:] = qkv[b, h*128 + t/16, (t%16)*64 .. +64).
__global__ __launch_bounds__(256, 2) void attn_tc(const float* __restrict__ qkv,
                                                  float* __restrict__ y) {
    extern __shared__ __align__(16) uint32_t smp[];
    // layout: Ks0|Ks1|Ks2 (64*68 each) | Vs0|Vs1|Vs2 (64*72 each)
    const int KSZ = 64 * 68, VSZ = 64 * 72;
    int bid = blockIdx.x;
    int qt = 15 - (bid >> 5);  // longest blocks first (LPT)
    int bh = bid & 31;
    int b = bh >> 4, h = bh & 15;
    int tid = threadIdx.x, lane = tid & 31, warp = tid >> 5;
    int g = lane >> 2, q4 = lane & 3;
    int r0 = qt * 128 + warp * 16 + g;
    int r1 = r0 + 8;

    const float* base = qkv + (size_t)b * T_ * NQKV;

    // staging constants (per thread: 4 K rows + 4 V rows, 16B each)
    int sr = tid >> 4, sc4 = (tid & 15) * 4;

    // Q fragments (remapped), pre-scaled by hs^-0.5 = 0.125
    uint32_t qa[8][4];
#pragma unroll
    for (int kk = 0; kk < 8; kk++) {
        int c0 = kk * 8 + q4;
        size_t a0 = (size_t)(h * 128 + (r0 >> 4)) * NQKV + (r0 & 15) * 64;
        size_t a1 = (size_t)(h * 128 + (r1 >> 4)) * NQKV + (r1 & 15) * 64;
        qa[kk][0] = f2tf(0.125f * base[a0 + c0]);
        qa[kk][1] = f2tf(0.125f * base[a1 + c0]);
        qa[kk][2] = f2tf(0.125f * base[a0 + c0 + 4]);
        qa[kk][3] = f2tf(0.125f * base[a1 + c0 + 4]);
    }

    float o[8][4];
#pragma unroll
    for (int j = 0; j < 8; j++)
#pragma unroll
        for (int e = 0; e < 4; e++) o[j][e] = 0.f;
    float m0 = -INFINITY, m1 = -INFINITY, l0 = 0.f, l1 = 0.f;

    int nkt = qt * 2 + 2;  // >= 2 always
    int wrmin = qt * 128 + warp * 16;
    int wrmax = wrmin + 15;
    int srcA = (lane & ~3) | (q4 >> 1);
    int srcB = srcA + 2;
    bool sel = (q4 & 1) != 0;

    // stage tile kt into 3-stage buffer bi (pure 16B async copies; data already tf32 bits)
    auto stage = [&](int kt, int bi) {
#pragma unroll
        for (int t = 0; t < 4; t++) {
            int r = sr + t * 16;
            size_t row = (size_t)(kt * 64 + r) * NQKV;
            cp16(smaddr(&smp[bi * KSZ + r * 68 + sc4]), &base[row + 1024 + sc4]);
            cp16(smaddr(&smp[3 * KSZ + bi * VSZ + r * 72 + sc4]), &base[row + 1088 + sc4]);
        }
        asm volatile("cp.async.commit_group;");
    };

    stage(0, 0);
    stage(1, 1);

    int cur = 0;   // buffer of tile kt
    int nxt = 2;   // buffer for tile kt+2
    for (int kt = 0; kt < nkt; kt++) {
        // tile kt ready when at most the groups newer than kt are pending
        if (kt + 1 < nkt) {
            asm volatile("cp.async.wait_group 1;");
        } else {
            asm volatile("cp.async.wait_group 0;");
        }
        __syncthreads();  // publishes tile kt; releases buffer nxt (read as tile kt-1)
        if (kt + 2 < nkt) stage(kt + 2, nxt);

        int ktb = kt * 64;
        if (ktb <= wrmax) {
            const uint32_t* Kc = smp + cur * KSZ;
            const uint32_t* Vc = smp + 3 * KSZ + cur * VSZ;

            // S = Q K^T (pre-scaled)
            float s[8][4];
#pragma unroll
            for (int j = 0; j < 8; j++)
#pragma unroll
                for (int e = 0; e < 4; e++) s[j][e] = 0.f;
#pragma unroll
            for (int kk = 0; kk < 8; kk++) {
#pragma unroll
                for (int j = 0; j < 8; j++) {
                    uint32_t bf[2];
                    bf[0] = Kc[(j * 8 + g) * 68 + kk * 8 + q4];
                    bf[1] = Kc[(j * 8 + g) * 68 + kk * 8 + q4 + 4];
                    mma_tf32(s[j], qa[kk], bf);
                }
            }

            // mask + online softmax (s reused as float probabilities)
            bool needmask = (ktb + 63) > wrmin;
            float t0 = -INFINITY, t1 = -INFINITY;
#pragma unroll
            for (int j = 0; j < 8; j++) {
                if (needmask) {
                    int tk = ktb + j * 8 + 2 * q4;
                    if (tk > r0) s[j][0] = -INFINITY;
                    if (tk + 1 > r0) s[j][1] = -INFINITY;
                    if (tk > r1) s[j][2] = -INFINITY;
                    if (tk + 1 > r1) s[j][3] = -INFINITY;
                }
                t0 = fmaxf(t0, fmaxf(s[j][0], s[j][1]));
                t1 = fmaxf(t1, fmaxf(s[j][2], s[j][3]));
            }
            t0 = fmaxf(t0, __shfl_xor_sync(0xffffffffu, t0, 1));
            t0 = fmaxf(t0, __shfl_xor_sync(0xffffffffu, t0, 2));
            t1 = fmaxf(t1, __shfl_xor_sync(0xffffffffu, t1, 1));
            t1 = fmaxf(t1, __shfl_xor_sync(0xffffffffu, t1, 2));
            float mn0 = fmaxf(m0, t0), mn1 = fmaxf(m1, t1);
            float cr0 = __expf(m0 - mn0), cr1 = __expf(m1 - mn1);
            m0 = mn0; m1 = mn1;
            l0 *= cr0; l1 *= cr1;
#pragma unroll
            for (int j = 0; j < 8; j++) {
                o[j][0] *= cr0; o[j][1] *= cr0;
                o[j][2] *= cr1; o[j][3] *= cr1;
            }
#pragma unroll
            for (int j = 0; j < 8; j++) {
                s[j][0] = __expf(s[j][0] - m0);
                s[j][1] = __expf(s[j][1] - m0);
                s[j][2] = __expf(s[j][2] - m1);
                s[j][3] = __expf(s[j][3] - m1);
                l0 += s[j][0] + s[j][1];
                l1 += s[j][2] + s[j][3];
            }

            // O += P V  (C-frag floats -> A-frag via quad shuffles, convert post-select)
#pragma unroll
            for (int kk = 0; kk < 8; kk++) {
                float x0 = __shfl_sync(0xffffffffu, s[kk][0], srcA);
                float x1 = __shfl_sync(0xffffffffu, s[kk][1], srcA);
                float x2 = __shfl_sync(0xffffffffu, s[kk][2], srcA);
                float x3 = __shfl_sync(0xffffffffu, s[kk][3], srcA);
                float y0 = __shfl_sync(0xffffffffu, s[kk][0], srcB);
                float y1 = __shfl_sync(0xffffffffu, s[kk][1], srcB);
                float y2 = __shfl_sync(0xffffffffu, s[kk][2], srcB);
                float y3 = __shfl_sync(0xffffffffu, s[kk][3], srcB);
                uint32_t pa[4];
                pa[0] = f2tf(sel ? x1 : x0);
                pa[1] = f2tf(sel ? x3 : x2);
                pa[2] = f2tf(sel ? y1 : y0);
                pa[3] = f2tf(sel ? y3 : y2);
#pragma unroll
                for (int j = 0; j < 8; j++) {
                    uint32_t bf[2];
                    bf[0] = Vc[(kk * 8 + q4) * 72 + j * 8 + g];
                    bf[1] = Vc[(kk * 8 + q4 + 4) * 72 + j * 8 + g];
                    mma_tf32(o[j], pa, bf);
                }
            }
        }
        cur = (cur == 2) ? 0 : cur + 1;
        nxt = (nxt == 2) ? 0 : nxt + 1;
    }

    l0 += __shfl_xor_sync(0xffffffffu, l0, 1);
    l0 += __shfl_xor_sync(0xffffffffu, l0, 2);
    l1 += __shfl_xor_sync(0xffffffffu, l1, 1);
    l1 += __shfl_xor_sync(0xffffffffu, l1, 2);
    float i0 = 1.f / l0, i1 = 1.f / l1;
    float* yb = y + (size_t)b * T_ * C_;
#pragma unroll
    for (int j = 0; j < 8; j++) {
        int col = h * 64 + j * 8 + 2 * q4;
        *(float2*)&yb[(size_t)r0 * C_ + col] = make_float2(o[j][0] * i0, o[j][1] * i0);
        *(float2*)&yb[(size_t)r1 * C_ + col] = make_float2(o[j][2] * i1, o[j][3] * i1);
    }
}

extern "C" void kernel_launch(void* const* d_in, const int* in_sizes, int n_in,
                              void* d_out, int out_size) {
    (void)in_sizes; (void)n_in; (void)out_size;
    const float* x  = (const float*)d_in[0];
    const float* Wk = (const float*)d_in[1];
    const float* Wv = (const float*)d_in[2];
    const float* Wq = (const float*)d_in[3];
    const float* Wp = (const float*)d_in[4];
    const float* bp = (const float*)d_in[5];
    float* out = (float*)d_out;

    float *qkvb, *yb;
    cudaGetSymbolAddress((void**)&qkvb, g_qkv);
    cudaGetSymbolAddress((void**)&yb, g_y);

    const int GEMM_SMEM = 4 * 128 * 36 * 4;                 // 73728 B
    const int ATTN_SMEM = 3 * (64 * 68 + 64 * 72) * 4;      // 107520 B
    cudaFuncSetAttribute(gemm_tc<false, true>,
                         cudaFuncAttributeMaxDynamicSharedMemorySize, GEMM_SMEM);
    cudaFuncSetAttribute(gemm_tc<true, false>,
                         cudaFuncAttributeMaxDynamicSharedMemorySize, GEMM_SMEM);
    cudaFuncSetAttribute(attn_tc,
                         cudaFuncAttributeMaxDynamicSharedMemorySize, ATTN_SMEM);

    // Fused qkv projection with inline weight concat: [4096,1152]; k/v cols -> tf32 bits
    gemm_tc<false, true><<<dim3(9, 32), 256, GEMM_SMEM>>>(x, Wq, Wk, Wv, nullptr, qkvb,
                                                          NQKV, 1024);
    // attention -> y [B,T,C] (head-transposed layout baked in)
    attn_tc<<<512, 256, ATTN_SMEM>>>(qkvb, yb);
    // out = y @ Wp.T + bp
    gemm_tc<true, false><<<dim3(8, 32), 256, GEMM_SMEM>>>(yb, Wp, nullptr, nullptr, bp, out,
                                                          1024, 1024);
}

// round 14
// speedup vs baseline: 1.5611x; 1.5611x over previous
#include <cuda_runtime.h>
#include <math.h>
#include <stdint.h>

#define B_ 2
#define T_ 2048
#define C_ 1024
#define H_ 16
#define HS_ 64
#define NQKV 1152  // 1024 q + 64 k + 64 v

// Scratch (allocation-free rule: __device__ globals). All tf32-bit patterns.
__device__ float g_xt[B_ * T_ * C_];
__device__ float g_wqkvt[NQKV * C_];
__device__ float g_wpt[C_ * C_];
__device__ float g_qkv[B_ * T_ * NQKV];  // q cols pre-scaled tf32 bits; k/v tf32 bits
__device__ float g_y[B_ * T_ * C_];      // attn output, tf32 bits

__device__ __forceinline__ uint32_t f2tf(float f) {
    uint32_t u;
    asm("cvt.rna.tf32.f32 %0, %1;" : "=r"(u) : "f"(f));
    return u;
}

__device__ __forceinline__ uint32_t smaddr(const void* p) {
    return (uint32_t)__cvta_generic_to_shared(p);
}

__device__ __forceinline__ void cp16(uint32_t s, const void* g) {
    asm volatile("cp.async.cg.shared.global [%0], [%1], 16;" :: "r"(s), "l"(g));
}

__device__ __forceinline__ void mma_tf32(float c[4], const uint32_t* a, const uint32_t* b) {
    asm volatile(
        "mma.sync.aligned.m16n8k8.row.col.f32.tf32.tf32.f32 "
        "{%0,%1,%2,%3}, {%4,%5,%6,%7}, {%8,%9}, {%0,%1,%2,%3};"
        : "+f"(c[0]), "+f"(c[1]), "+f"(c[2]), "+f"(c[3])
        : "r"(a[0]), "r"(a[1]), "r"(a[2]), "r"(a[3]), "r"(b[0]), "r"(b[1]));
}

// One-shot rna tf32 conversion of x, concat(Wq,Wk,Wv), Wp. 1,605,632 float4s.
__global__ __launch_bounds__(256) void conv_tf(const float* __restrict__ x,
                                               const float* __restrict__ Wk,
                                               const float* __restrict__ Wv,
                                               const float* __restrict__ Wq,
                                               const float* __restrict__ Wp,
                                               float* __restrict__ xt,
                                               float* __restrict__ wqkvt,
                                               float* __restrict__ wpt) {
    int idx = blockIdx.x * 256 + threadIdx.x;
    const int X4 = B_ * T_ * C_ / 4;      // 1048576
    const int WQKV4 = NQKV * C_ / 4;      // 294912
    float4 f;
    float4* dst;
    if (idx < X4) {
        f = ((const float4*)x)[idx];
        dst = (float4*)xt + idx;
    } else if (idx < X4 + WQKV4) {
        int w4 = idx - X4;
        int row = w4 >> 8, c4 = w4 & 255;
        const float4* src = row < 1024 ? (const float4*)Wq + row * 256 + c4
                          : row < 1088 ? (const float4*)Wk + (row - 1024) * 256 + c4
                                       : (const float4*)Wv + (row - 1088) * 256 + c4;
        f = *src;
        dst = (float4*)wqkvt + w4;
    } else {
        int w4 = idx - X4 - WQKV4;
        f = ((const float4*)Wp)[w4];
        dst = (float4*)wpt + w4;
    }
    *(uint4*)dst = make_uint4(f2tf(f.x), f2tf(f.y), f2tf(f.z), f2tf(f.w));
}

// C[m,n] = sum_k A[m,k]*W[n,k] (+bias). A/W are tf32 bits -> pure cp.async staging.
// BM=128, BK=32, BN=128; 256 thr = 8 warps (4m x 2n).
// 3-stage cp.async pipeline, ONE barrier per K-iter (3-buffer scheme).
// QKVEPI: cols<1024 (q) stored as f2tf(0.125*acc); cols>=1024 (k/v) as f2tf(acc).
template <bool BIAS, bool QKVEPI>
__global__ __launch_bounds__(256) void gemm_cp(const uint32_t* __restrict__ A,
                                               const uint32_t* __restrict__ W,
                                               const float* __restrict__ bias,
                                               float* __restrict__ C,
                                               int N, int K) {
    extern __shared__ __align__(16) uint32_t smp[];
    const int TSZ = 128 * 36;  // As0|As1|As2 | Bs0|Bs1|Bs2
    int tid = threadIdx.x, lane = tid & 31, warp = tid >> 5;
    int g = lane >> 2, q4 = lane & 3;
    int wm = warp & 3, wn = warp >> 2;
    int bm = blockIdx.y * 128, bn = blockIdx.x * 128;
    int lr = tid >> 3, lc4 = (tid & 7) * 4;

    float acc[2][8][4];
#pragma unroll
    for (int mt = 0; mt < 2; mt++)
#pragma unroll
        for (int j = 0; j < 8; j++)
#pragma unroll
            for (int e = 0; e < 4; e++) acc[mt][j][e] = 0.f;

    const uint32_t* abase = A + (size_t)(bm + lr) * K + lc4;
    const uint32_t* wbase = W + (size_t)(bn + lr) * K + lc4;

    int nit = K >> 5;  // K/32 iterations

    auto stage = [&](int it, int bi) {
        int k0 = it * 32;
#pragma unroll
        for (int t = 0; t < 4; t++) {
            cp16(smaddr(&smp[bi * TSZ + (lr + t * 32) * 36 + lc4]),
                 abase + (size_t)t * 32 * K + k0);
            cp16(smaddr(&smp[3 * TSZ + bi * TSZ + (lr + t * 32) * 36 + lc4]),
                 wbase + (size_t)t * 32 * K + k0);
        }
        asm volatile("cp.async.commit_group;");
    };

    stage(0, 0);
    stage(1, 1);

    int cur = 0, nxt = 2;
    for (int it = 0; it < nit; it++) {
        if (it + 1 < nit) {
            asm volatile("cp.async.wait_group 1;");
        } else {
            asm volatile("cp.async.wait_group 0;");
        }
        __syncthreads();  // publishes tile it; releases buffer nxt
        if (it + 2 < nit) stage(it + 2, nxt);

        const uint32_t* Asb = smp + cur * TSZ;
        const uint32_t* Bsb = smp + 3 * TSZ + cur * TSZ;
#pragma unroll
        for (int kk = 0; kk < 4; kk++) {
            uint32_t af[2][4], bf[8][2];
#pragma unroll
            for (int mt = 0; mt < 2; mt++) {
                int rb = wm * 32 + mt * 16;
                af[mt][0] = Asb[(rb + g) * 36 + kk * 8 + q4];
                af[mt][1] = Asb[(rb + g + 8) * 36 + kk * 8 + q4];
                af[mt][2] = Asb[(rb + g) * 36 + kk * 8 + q4 + 4];
                af[mt][3] = Asb[(rb + g + 8) * 36 + kk * 8 + q4 + 4];
            }
#pragma unroll
            for (int j = 0; j < 8; j++) {
                int nb = wn * 64 + j * 8 + g;
                bf[j][0] = Bsb[nb * 36 + kk * 8 + q4];
                bf[j][1] = Bsb[nb * 36 + kk * 8 + q4 + 4];
            }
#pragma unroll
            for (int mt = 0; mt < 2; mt++)
#pragma unroll
                for (int j = 0; j < 8; j++) mma_tf32(acc[mt][j], af[mt], bf[j]);
        }
        cur = (cur == 2) ? 0 : cur + 1;
        nxt = (nxt == 2) ? 0 : nxt + 1;
    }

#pragma unroll
    for (int mt = 0; mt < 2; mt++)
#pragma unroll
        for (int j = 0; j < 8; j++) {
            int row = bm + wm * 32 + mt * 16 + g;
            int col = bn + wn * 64 + j * 8 + 2 * q4;
            float2 v0 = make_float2(acc[mt][j][0], acc[mt][j][1]);
            float2 v1 = make_float2(acc[mt][j][2], acc[mt][j][3]);
            if (BIAS) {
                float b0 = bias[col], b1 = bias[col + 1];
                v0.x += b0; v0.y += b1; v1.x += b0; v1.y += b1;
            }
            if (QKVEPI) {
                float sc = (col < 1024) ? 0.125f : 1.0f;
                v0.x = __uint_as_float(f2tf(sc * v0.x));
                v0.y = __uint_as_float(f2tf(sc * v0.y));
                v1.x = __uint_as_float(f2tf(sc * v1.x));
                v1.y = __uint_as_float(f2tf(sc * v1.y));
            }
            *(float2*)&C[(size_t)row * N + col] = v0;
            *(float2*)&C[(size_t)(row + 8) * N + col] = v1;
        }
}

// Flash-style causal MQA attention, tf32 tensor cores (round-6 structure).
// 256 thr = 8 warps; each warp owns 16 query rows. 64-key 2-stage cp.async tiles.
// q/K/V arrive pre-converted tf32 bits (q pre-scaled by 0.125); y emitted as tf32 bits.
// q remap quirk: q[b,h,t,:] = qkv[b, h*128 + t/16, (t%16)*64 .. +64).
__global__ __launch_bounds__(256, 2) void attn_tc(const uint32_t* __restrict__ qkv,
                                                  uint32_t* __restrict__ y) {
    extern __shared__ __align__(16) uint32_t smp[];
    const int KSZ = 64 * 68, VSZ = 64 * 72;  // Ks0|Ks1|Vs0|Vs1
    int bid = blockIdx.x;
    int qt = 15 - (bid >> 5);  // LPT
    int bh = bid & 31;
    int b = bh >> 4, h = bh & 15;
    int tid = threadIdx.x, lane = tid & 31, warp = tid >> 5;
    int g = lane >> 2, q4 = lane & 3;
    int r0 = qt * 128 + warp * 16 + g;
    int r1 = r0 + 8;

    const uint32_t* base = qkv + (size_t)b * T_ * NQKV;
    int sr = tid >> 4, sc4 = (tid & 15) * 4;

    uint32_t qa[8][4];
#pragma unroll
    for (int kk = 0; kk < 8; kk++) {
        int c0 = kk * 8 + q4;
        size_t a0 = (size_t)(h * 128 + (r0 >> 4)) * NQKV + (r0 & 15) * 64;
        size_t a1 = (size_t)(h * 128 + (r1 >> 4)) * NQKV + (r1 & 15) * 64;
        qa[kk][0] = base[a0 + c0];
        qa[kk][1] = base[a1 + c0];
        qa[kk][2] = base[a0 + c0 + 4];
        qa[kk][3] = base[a1 + c0 + 4];
    }

    float o[8][4];
#pragma unroll
    for (int j = 0; j < 8; j++)
#pragma unroll
        for (int e = 0; e < 4; e++) o[j][e] = 0.f;
    float m0 = -INFINITY, m1 = -INFINITY, l0 = 0.f, l1 = 0.f;

    int nkt = qt * 2 + 2;
    int wrmin = qt * 128 + warp * 16;
    int wrmax = wrmin + 15;
    int srcA = (lane & ~3) | (q4 >> 1);
    int srcB = srcA + 2;
    bool sel = (q4 & 1) != 0;

    auto stage = [&](int kt, int bi) {
#pragma unroll
        for (int t = 0; t < 4; t++) {
            int r = sr + t * 16;
            size_t row = (size_t)(kt * 64 + r) * NQKV;
            cp16(smaddr(&smp[bi * KSZ + r * 68 + sc4]), base + row + 1024 + sc4);
            cp16(smaddr(&smp[2 * KSZ + bi * VSZ + r * 72 + sc4]), base + row + 1088 + sc4);
        }
        asm volatile("cp.async.commit_group;");
    };

    stage(0, 0);

    for (int kt = 0; kt < nkt; kt++) {
        if (kt + 1 < nkt) {
            stage(kt + 1, (kt + 1) & 1);
            asm volatile("cp.async.wait_group 1;");
        } else {
            asm volatile("cp.async.wait_group 0;");
        }
        __syncthreads();

        int ktb = kt * 64;
        if (ktb <= wrmax) {
            const uint32_t* Kc = smp + (kt & 1) * KSZ;
            const uint32_t* Vc = smp + 2 * KSZ + (kt & 1) * VSZ;

            float s[8][4];
#pragma unroll
            for (int j = 0; j < 8; j++)
#pragma unroll
                for (int e = 0; e < 4; e++) s[j][e] = 0.f;
#pragma unroll
            for (int kk = 0; kk < 8; kk++) {
#pragma unroll
                for (int j = 0; j < 8; j++) {
                    uint32_t bf[2];
                    bf[0] = Kc[(j * 8 + g) * 68 + kk * 8 + q4];
                    bf[1] = Kc[(j * 8 + g) * 68 + kk * 8 + q4 + 4];
                    mma_tf32(s[j], qa[kk], bf);
                }
            }

            bool needmask = (ktb + 63) > wrmin;
            float t0 = -INFINITY, t1 = -INFINITY;
#pragma unroll
            for (int j = 0; j < 8; j++) {
                if (needmask) {
                    int tk = ktb + j * 8 + 2 * q4;
                    if (tk > r0) s[j][0] = -INFINITY;
                    if (tk + 1 > r0) s[j][1] = -INFINITY;
                    if (tk > r1) s[j][2] = -INFINITY;
                    if (tk + 1 > r1) s[j][3] = -INFINITY;
                }
                t0 = fmaxf(t0, fmaxf(s[j][0], s[j][1]));
                t1 = fmaxf(t1, fmaxf(s[j][2], s[j][3]));
            }
            t0 = fmaxf(t0, __shfl_xor_sync(0xffffffffu, t0, 1));
            t0 = fmaxf(t0, __shfl_xor_sync(0xffffffffu, t0, 2));
            t1 = fmaxf(t1, __shfl_xor_sync(0xffffffffu, t1, 1));
            t1 = fmaxf(t1, __shfl_xor_sync(0xffffffffu, t1, 2));
            float mn0 = fmaxf(m0, t0), mn1 = fmaxf(m1, t1);
            float cr0 = __expf(m0 - mn0), cr1 = __expf(m1 - mn1);
            m0 = mn0; m1 = mn1;
            l0 *= cr0; l1 *= cr1;
#pragma unroll
            for (int j = 0; j < 8; j++) {
                o[j][0] *= cr0; o[j][1] *= cr0;
                o[j][2] *= cr1; o[j][3] *= cr1;
            }
#pragma unroll
            for (int j = 0; j < 8; j++) {
                s[j][0] = __expf(s[j][0] - m0);
                s[j][1] = __expf(s[j][1] - m0);
                s[j][2] = __expf(s[j][2] - m1);
                s[j][3] = __expf(s[j][3] - m1);
                l0 += s[j][0] + s[j][1];
                l1 += s[j][2] + s[j][3];
            }

#pragma unroll
            for (int kk = 0; kk < 8; kk++) {
                float x0 = __shfl_sync(0xffffffffu, s[kk][0], srcA);
                float x1 = __shfl_sync(0xffffffffu, s[kk][1], srcA);
                float x2 = __shfl_sync(0xffffffffu, s[kk][2], srcA);
                float x3 = __shfl_sync(0xffffffffu, s[kk][3], srcA);
                float y0 = __shfl_sync(0xffffffffu, s[kk][0], srcB);
                float y1 = __shfl_sync(0xffffffffu, s[kk][1], srcB);
                float y2 = __shfl_sync(0xffffffffu, s[kk][2], srcB);
                float y3 = __shfl_sync(0xffffffffu, s[kk][3], srcB);
                uint32_t pa[4];
                pa[0] = f2tf(sel ? x1 : x0);
                pa[1] = f2tf(sel ? x3 : x2);
                pa[2] = f2tf(sel ? y1 : y0);
                pa[3] = f2tf(sel ? y3 : y2);
#pragma unroll
                for (int j = 0; j < 8; j++) {
                    uint32_t bf[2];
                    bf[0] = Vc[(kk * 8 + q4) * 72 + j * 8 + g];
                    bf[1] = Vc[(kk * 8 + q4 + 4) * 72 + j * 8 + g];
                    mma_tf32(o[j], pa, bf);
                }
            }
        }
        __syncthreads();
    }

    l0 += __shfl_xor_sync(0xffffffffu, l0, 1);
    l0 += __shfl_xor_sync(0xffffffffu, l0, 2);
    l1 += __shfl_xor_sync(0xffffffffu, l1, 1);
    l1 += __shfl_xor_sync(0xffffffffu, l1, 2);
    float i0 = 1.f / l0, i1 = 1.f / l1;
    uint32_t* yb = y + (size_t)b * T_ * C_;
#pragma unroll
    for (int j = 0; j < 8; j++) {
        int col = h * 64 + j * 8 + 2 * q4;
        *(uint2*)&yb[(size_t)r0 * C_ + col] =
            make_uint2(f2tf(o[j][0] * i0), f2tf(o[j][1] * i0));
        *(uint2*)&yb[(size_t)r1 * C_ + col] =
            make_uint2(f2tf(o[j][2] * i1), f2tf(o[j][3] * i1));
    }
}

extern "C" void kernel_launch(void* const* d_in, const int* in_sizes, int n_in,
                              void* d_out, int out_size) {
    (void)in_sizes; (void)n_in; (void)out_size;
    const float* x  = (const float*)d_in[0];
    const float* Wk = (const float*)d_in[1];
    const float* Wv = (const float*)d_in[2];
    const float* Wq = (const float*)d_in[3];
    const float* Wp = (const float*)d_in[4];
    const float* bp = (const float*)d_in[5];
    float* out = (float*)d_out;

    float *xt, *wqkvt, *wpt, *qkvb, *yb;
    cudaGetSymbolAddress((void**)&xt, g_xt);
    cudaGetSymbolAddress((void**)&wqkvt, g_wqkvt);
    cudaGetSymbolAddress((void**)&wpt, g_wpt);
    cudaGetSymbolAddress((void**)&qkvb, g_qkv);
    cudaGetSymbolAddress((void**)&yb, g_y);

    const int GEMM_SMEM = 6 * 128 * 36 * 4;                 // 110592 B (3 stages x A,B)
    const int ATTN_SMEM = (2 * 64 * 68 + 2 * 64 * 72) * 4;  // 71680 B
    cudaFuncSetAttribute(gemm_cp<false, true>,
                         cudaFuncAttributeMaxDynamicSharedMemorySize, GEMM_SMEM);
    cudaFuncSetAttribute(gemm_cp<true, false>,
                         cudaFuncAttributeMaxDynamicSharedMemorySize, GEMM_SMEM);
    cudaFuncSetAttribute(attn_tc,
                         cudaFuncAttributeMaxDynamicSharedMemorySize, ATTN_SMEM);

    // One-shot tf32 conversion of all GEMM inputs (x, Wq‖Wk‖Wv, Wp)
    conv_tf<<<6272, 256>>>(x, Wk, Wv, Wq, Wp, xt, wqkvt, wpt);
    // Fused qkv projection: [4096,1152]; epilogue emits tf32 bits (q pre-scaled 0.125)
    gemm_cp<false, true><<<dim3(9, 32), 256, GEMM_SMEM>>>((const uint32_t*)xt,
                                                          (const uint32_t*)wqkvt, nullptr,
                                                          qkvb, NQKV, 1024);
    // attention -> y (tf32 bits, head-transposed layout baked in)
    attn_tc<<<512, 256, ATTN_SMEM>>>((const uint32_t*)qkvb, (uint32_t*)yb);
    // out = y @ Wp.T + bp (fp32 output)
    gemm_cp<true, false><<<dim3(8, 32), 256, GEMM_SMEM>>>((const uint32_t*)yb,
                                                          (const uint32_t*)wpt, bp, out,
                                                          1024, 1024);
}

// round 15
// speedup vs baseline: 1.5819x; 1.0134x over previous
#include <cuda_runtime.h>
#include <math.h>
#include <stdint.h>

#define B_ 2
#define T_ 2048
#define C_ 1024
#define H_ 16
#define HS_ 64
#define NQKV 1152  // 1024 q + 64 k + 64 v

// Scratch (allocation-free rule: __device__ globals). All tf32-bit patterns.
__device__ float g_xt[B_ * T_ * C_];
__device__ float g_wqkvt[NQKV * C_];
__device__ float g_wpt[C_ * C_];
__device__ float g_qkv[B_ * T_ * NQKV];  // q cols pre-scaled tf32 bits; k/v tf32 bits
__device__ float g_y[B_ * T_ * C_];      // attn output, tf32 bits

__device__ __forceinline__ uint32_t f2tf(float f) {
    uint32_t u;
    asm("cvt.rna.tf32.f32 %0, %1;" : "=r"(u) : "f"(f));
    return u;
}

__device__ __forceinline__ uint32_t smaddr(const void* p) {
    return (uint32_t)__cvta_generic_to_shared(p);
}

__device__ __forceinline__ void cp16(uint32_t s, const void* g) {
    asm volatile("cp.async.cg.shared.global [%0], [%1], 16;" :: "r"(s), "l"(g));
}

__device__ __forceinline__ void ldm_x4(uint32_t r[4], uint32_t a) {
    asm volatile("ldmatrix.sync.aligned.m8n8.x4.shared.b16 {%0,%1,%2,%3}, [%4];"
                 : "=r"(r[0]), "=r"(r[1]), "=r"(r[2]), "=r"(r[3]) : "r"(a));
}

__device__ __forceinline__ void mma_tf32(float c[4], const uint32_t* a, const uint32_t* b) {
    asm volatile(
        "mma.sync.aligned.m16n8k8.row.col.f32.tf32.tf32.f32 "
        "{%0,%1,%2,%3}, {%4,%5,%6,%7}, {%8,%9}, {%0,%1,%2,%3};"
        : "+f"(c[0]), "+f"(c[1]), "+f"(c[2]), "+f"(c[3])
        : "r"(a[0]), "r"(a[1]), "r"(a[2]), "r"(a[3]), "r"(b[0]), "r"(b[1]));
}

// One-shot rna tf32 conversion of x, concat(Wq,Wk,Wv), Wp. 1,605,632 float4s.
__global__ __launch_bounds__(256) void conv_tf(const float* __restrict__ x,
                                               const float* __restrict__ Wk,
                                               const float* __restrict__ Wv,
                                               const float* __restrict__ Wq,
                                               const float* __restrict__ Wp,
                                               float* __restrict__ xt,
                                               float* __restrict__ wqkvt,
                                               float* __restrict__ wpt) {
    int idx = blockIdx.x * 256 + threadIdx.x;
    const int X4 = B_ * T_ * C_ / 4;      // 1048576
    const int WQKV4 = NQKV * C_ / 4;      // 294912
    float4 f;
    float4* dst;
    if (idx < X4) {
        f = ((const float4*)x)[idx];
        dst = (float4*)xt + idx;
    } else if (idx < X4 + WQKV4) {
        int w4 = idx - X4;
        int row = w4 >> 8, c4 = w4 & 255;
        const float4* src = row < 1024 ? (const float4*)Wq + row * 256 + c4
                          : row < 1088 ? (const float4*)Wk + (row - 1024) * 256 + c4
                                       : (const float4*)Wv + (row - 1088) * 256 + c4;
        f = *src;
        dst = (float4*)wqkvt + w4;
    } else {
        int w4 = idx - X4 - WQKV4;
        f = ((const float4*)Wp)[w4];
        dst = (float4*)wpt + w4;
    }
    *(uint4*)dst = make_uint4(f2tf(f.x), f2tf(f.y), f2tf(f.z), f2tf(f.w));
}

// C[m,n] = sum_k A[m,k]*W[n,k] (+bias). A/W tf32 bits -> pure cp.async staging.
// BM=128, BK=32, BN=128; 256 thr = 8 warps (4m x 2n).
// 3-stage cp.async pipeline, ONE barrier per K-iter; ldmatrix fragment loads.
// QKVEPI: cols<1024 (q) stored as f2tf(0.125*acc); cols>=1024 (k/v) as f2tf(acc).
template <bool BIAS, bool QKVEPI>
__global__ __launch_bounds__(256) void gemm_cp(const uint32_t* __restrict__ A,
                                               const uint32_t* __restrict__ W,
                                               const float* __restrict__ bias,
                                               float* __restrict__ C,
                                               int N, int K) {
    extern __shared__ __align__(16) uint32_t smp[];
    const int TSZ = 128 * 36;  // As0|As1|As2 | Bs0|Bs1|Bs2
    int tid = threadIdx.x, lane = tid & 31, warp = tid >> 5;
    int g = lane >> 2, q4 = lane & 3;
    int wm = warp & 3, wn = warp >> 2;
    int bm = blockIdx.y * 128, bn = blockIdx.x * 128;
    int lr = tid >> 3, lc4 = (tid & 7) * 4;

    // ldmatrix per-lane word offsets within a tile buffer (R5-proven mapping)
    int aRow = wm * 32 + (lane & 15);
    int aCol = (lane >> 4) * 4;
    uint32_t aoff = (uint32_t)(aRow * 36 + aCol);
    int bRow = wn * 64 + (lane & 7) + ((lane >> 4) << 3);
    int bCol = ((lane >> 3) & 1) * 4;
    uint32_t boff = (uint32_t)(bRow * 36 + bCol);
    uint32_t smbase = smaddr(smp);

    float acc[2][8][4];
#pragma unroll
    for (int mt = 0; mt < 2; mt++)
#pragma unroll
        for (int j = 0; j < 8; j++)
#pragma unroll
            for (int e = 0; e < 4; e++) acc[mt][j][e] = 0.f;

    const uint32_t* abase = A + (size_t)(bm + lr) * K + lc4;
    const uint32_t* wbase = W + (size_t)(bn + lr) * K + lc4;

    int nit = K >> 5;

    auto stage = [&](int it, int bi) {
        int k0 = it * 32;
#pragma unroll
        for (int t = 0; t < 4; t++) {
            cp16(smaddr(&smp[bi * TSZ + (lr + t * 32) * 36 + lc4]),
                 abase + (size_t)t * 32 * K + k0);
            cp16(smaddr(&smp[3 * TSZ + bi * TSZ + (lr + t * 32) * 36 + lc4]),
                 wbase + (size_t)t * 32 * K + k0);
        }
        asm volatile("cp.async.commit_group;");
    };

    stage(0, 0);
    stage(1, 1);

    int cur = 0, nxt = 2;
    for (int it = 0; it < nit; it++) {
        if (it + 1 < nit) {
            asm volatile("cp.async.wait_group 1;");
        } else {
            asm volatile("cp.async.wait_group 0;");
        }
        __syncthreads();  // publishes tile it; releases buffer nxt
        if (it + 2 < nit) stage(it + 2, nxt);

        uint32_t abuf = smbase + (uint32_t)(cur * TSZ) * 4u + aoff * 4u;
        uint32_t bbuf = smbase + (uint32_t)((3 + cur) * TSZ) * 4u + boff * 4u;
#pragma unroll
        for (int kk = 0; kk < 4; kk++) {
            uint32_t af[2][4], bfr[4][4];
#pragma unroll
            for (int mt = 0; mt < 2; mt++)
                ldm_x4(af[mt], abuf + (uint32_t)(mt * 16 * 36 + kk * 8) * 4u);
#pragma unroll
            for (int jp = 0; jp < 4; jp++)
                ldm_x4(bfr[jp], bbuf + (uint32_t)(jp * 16 * 36 + kk * 8) * 4u);
#pragma unroll
            for (int mt = 0; mt < 2; mt++)
#pragma unroll
                for (int j = 0; j < 8; j++)
                    mma_tf32(acc[mt][j], af[mt], &bfr[j >> 1][(j & 1) * 2]);
        }
        cur = (cur == 2) ? 0 : cur + 1;
        nxt = (nxt == 2) ? 0 : nxt + 1;
    }

#pragma unroll
    for (int mt = 0; mt < 2; mt++)
#pragma unroll
        for (int j = 0; j < 8; j++) {
            int row = bm + wm * 32 + mt * 16 + g;
            int col = bn + wn * 64 + j * 8 + 2 * q4;
            float2 v0 = make_float2(acc[mt][j][0], acc[mt][j][1]);
            float2 v1 = make_float2(acc[mt][j][2], acc[mt][j][3]);
            if (BIAS) {
                float b0 = bias[col], b1 = bias[col + 1];
                v0.x += b0; v0.y += b1; v1.x += b0; v1.y += b1;
            }
            if (QKVEPI) {
                float sc = (col < 1024) ? 0.125f : 1.0f;
                v0.x = __uint_as_float(f2tf(sc * v0.x));
                v0.y = __uint_as_float(f2tf(sc * v0.y));
                v1.x = __uint_as_float(f2tf(sc * v1.x));
                v1.y = __uint_as_float(f2tf(sc * v1.y));
            }
            *(float2*)&C[(size_t)row * N + col] = v0;
            *(float2*)&C[(size_t)(row + 8) * N + col] = v1;
        }
}

// Flash-style causal MQA attention, tf32 tensor cores (round-14 proven form).
// 256 thr = 8 warps; each warp owns 16 query rows. 64-key 2-stage cp.async tiles.
// q/K/V arrive pre-converted tf32 bits (q pre-scaled by 0.125); y emitted as tf32 bits.
// q remap quirk: q[b,h,t,:] = qkv[b, h*128 + t/16, (t%16)*64 .. +64).
__global__ __launch_bounds__(256, 2) void attn_tc(const uint32_t* __restrict__ qkv,
                                                  uint32_t* __restrict__ y) {
    extern __shared__ __align__(16) uint32_t smp[];
    const int KSZ = 64 * 68, VSZ = 64 * 72;  // Ks0|Ks1|Vs0|Vs1
    int bid = blockIdx.x;
    int qt = 15 - (bid >> 5);  // LPT
    int bh = bid & 31;
    int b = bh >> 4, h = bh & 15;
    int tid = threadIdx.x, lane = tid & 31, warp = tid >> 5;
    int g = lane >> 2, q4 = lane & 3;
    int r0 = qt * 128 + warp * 16 + g;
    int r1 = r0 + 8;

    const uint32_t* base = qkv + (size_t)b * T_ * NQKV;
    int sr = tid >> 4, sc4 = (tid & 15) * 4;

    uint32_t qa[8][4];
#pragma unroll
    for (int kk = 0; kk < 8; kk++) {
        int c0 = kk * 8 + q4;
        size_t a0 = (size_t)(h * 128 + (r0 >> 4)) * NQKV + (r0 & 15) * 64;
        size_t a1 = (size_t)(h * 128 + (r1 >> 4)) * NQKV + (r1 & 15) * 64;
        qa[kk][0] = base[a0 + c0];
        qa[kk][1] = base[a1 + c0];
        qa[kk][2] = base[a0 + c0 + 4];
        qa[kk][3] = base[a1 + c0 + 4];
    }

    float o[8][4];
#pragma unroll
    for (int j = 0; j < 8; j++)
#pragma unroll
        for (int e = 0; e < 4; e++) o[j][e] = 0.f;
    float m0 = -INFINITY, m1 = -INFINITY, l0 = 0.f, l1 = 0.f;

    int nkt = qt * 2 + 2;
    int wrmin = qt * 128 + warp * 16;
    int wrmax = wrmin + 15;
    int srcA = (lane & ~3) | (q4 >> 1);
    int srcB = srcA + 2;
    bool sel = (q4 & 1) != 0;

    auto stage = [&](int kt, int bi) {
#pragma unroll
        for (int t = 0; t < 4; t++) {
            int r = sr + t * 16;
            size_t row = (size_t)(kt * 64 + r) * NQKV;
            cp16(smaddr(&smp[bi * KSZ + r * 68 + sc4]), base + row + 1024 + sc4);
            cp16(smaddr(&smp[2 * KSZ + bi * VSZ + r * 72 + sc4]), base + row + 1088 + sc4);
        }
        asm volatile("cp.async.commit_group;");
    };

    stage(0, 0);

    for (int kt = 0; kt < nkt; kt++) {
        if (kt + 1 < nkt) {
            stage(kt + 1, (kt + 1) & 1);
            asm volatile("cp.async.wait_group 1;");
        } else {
            asm volatile("cp.async.wait_group 0;");
        }
        __syncthreads();

        int ktb = kt * 64;
        if (ktb <= wrmax) {
            const uint32_t* Kc = smp + (kt & 1) * KSZ;
            const uint32_t* Vc = smp + 2 * KSZ + (kt & 1) * VSZ;

            float s[8][4];
#pragma unroll
            for (int j = 0; j < 8; j++)
#pragma unroll
                for (int e = 0; e < 4; e++) s[j][e] = 0.f;
#pragma unroll
            for (int kk = 0; kk < 8; kk++) {
#pragma unroll
                for (int j = 0; j < 8; j++) {
                    uint32_t bf[2];
                    bf[0] = Kc[(j * 8 + g) * 68 + kk * 8 + q4];
                    bf[1] = Kc[(j * 8 + g) * 68 + kk * 8 + q4 + 4];
                    mma_tf32(s[j], qa[kk], bf);
                }
            }

            bool needmask = (ktb + 63) > wrmin;
            float t0 = -INFINITY, t1 = -INFINITY;
#pragma unroll
            for (int j = 0; j < 8; j++) {
                if (needmask) {
                    int tk = ktb + j * 8 + 2 * q4;
                    if (tk > r0) s[j][0] = -INFINITY;
                    if (tk + 1 > r0) s[j][1] = -INFINITY;
                    if (tk > r1) s[j][2] = -INFINITY;
                    if (tk + 1 > r1) s[j][3] = -INFINITY;
                }
                t0 = fmaxf(t0, fmaxf(s[j][0], s[j][1]));
                t1 = fmaxf(t1, fmaxf(s[j][2], s[j][3]));
            }
            t0 = fmaxf(t0, __shfl_xor_sync(0xffffffffu, t0, 1));
            t0 = fmaxf(t0, __shfl_xor_sync(0xffffffffu, t0, 2));
            t1 = fmaxf(t1, __shfl_xor_sync(0xffffffffu, t1, 1));
            t1 = fmaxf(t1, __shfl_xor_sync(0xffffffffu, t1, 2));
            float mn0 = fmaxf(m0, t0), mn1 = fmaxf(m1, t1);
            float cr0 = __expf(m0 - mn0), cr1 = __expf(m1 - mn1);
            m0 = mn0; m1 = mn1;
            l0 *= cr0; l1 *= cr1;
#pragma unroll
            for (int j = 0; j < 8; j++) {
                o[j][0] *= cr0; o[j][1] *= cr0;
                o[j][2] *= cr1; o[j][3] *= cr1;
            }
#pragma unroll
            for (int j = 0; j < 8; j++) {
                s[j][0] = __expf(s[j][0] - m0);
                s[j][1] = __expf(s[j][1] - m0);
                s[j][2] = __expf(s[j][2] - m1);
                s[j][3] = __expf(s[j][3] - m1);
                l0 += s[j][0] + s[j][1];
                l1 += s[j][2] + s[j][3];
            }

#pragma unroll
            for (int kk = 0; kk < 8; kk++) {
                float x0 = __shfl_sync(0xffffffffu, s[kk][0], srcA);
                float x1 = __shfl_sync(0xffffffffu, s[kk][1], srcA);
                float x2 = __shfl_sync(0xffffffffu, s[kk][2], srcA);
                float x3 = __shfl_sync(0xffffffffu, s[kk][3], srcA);
                float y0 = __shfl_sync(0xffffffffu, s[kk][0], srcB);
                float y1 = __shfl_sync(0xffffffffu, s[kk][1], srcB);
                float y2 = __shfl_sync(0xffffffffu, s[kk][2], srcB);
                float y3 = __shfl_sync(0xffffffffu, s[kk][3], srcB);
                uint32_t pa[4];
                pa[0] = f2tf(sel ? x1 : x0);
                pa[1] = f2tf(sel ? x3 : x2);
                pa[2] = f2tf(sel ? y1 : y0);
                pa[3] = f2tf(sel ? y3 : y2);
#pragma unroll
                for (int j = 0; j < 8; j++) {
                    uint32_t bf[2];
                    bf[0] = Vc[(kk * 8 + q4) * 72 + j * 8 + g];
                    bf[1] = Vc[(kk * 8 + q4 + 4) * 72 + j * 8 + g];
                    mma_tf32(o[j], pa, bf);
                }
            }
        }
        __syncthreads();
    }

    l0 += __shfl_xor_sync(0xffffffffu, l0, 1);
    l0 += __shfl_xor_sync(0xffffffffu, l0, 2);
    l1 += __shfl_xor_sync(0xffffffffu, l1, 1);
    l1 += __shfl_xor_sync(0xffffffffu, l1, 2);
    float i0 = 1.f / l0, i1 = 1.f / l1;
    uint32_t* yb = y + (size_t)b * T_ * C_;
#pragma unroll
    for (int j = 0; j < 8; j++) {
        int col = h * 64 + j * 8 + 2 * q4;
        *(uint2*)&yb[(size_t)r0 * C_ + col] =
            make_uint2(f2tf(o[j][0] * i0), f2tf(o[j][1] * i0));
        *(uint2*)&yb[(size_t)r1 * C_ + col] =
            make_uint2(f2tf(o[j][2] * i1), f2tf(o[j][3] * i1));
    }
}

extern "C" void kernel_launch(void* const* d_in, const int* in_sizes, int n_in,
                              void* d_out, int out_size) {
    (void)in_sizes; (void)n_in; (void)out_size;
    const float* x  = (const float*)d_in[0];
    const float* Wk = (const float*)d_in[1];
    const float* Wv = (const float*)d_in[2];
    const float* Wq = (const float*)d_in[3];
    const float* Wp = (const float*)d_in[4];
    const float* bp = (const float*)d_in[5];
    float* out = (float*)d_out;

    float *xt, *wqkvt, *wpt, *qkvb, *yb;
    cudaGetSymbolAddress((void**)&xt, g_xt);
    cudaGetSymbolAddress((void**)&wqkvt, g_wqkvt);
    cudaGetSymbolAddress((void**)&wpt, g_wpt);
    cudaGetSymbolAddress((void**)&qkvb, g_qkv);
    cudaGetSymbolAddress((void**)&yb, g_y);

    const int GEMM_SMEM = 6 * 128 * 36 * 4;                 // 110592 B
    const int ATTN_SMEM = (2 * 64 * 68 + 2 * 64 * 72) * 4;  // 71680 B
    cudaFuncSetAttribute(gemm_cp<false, true>,
                         cudaFuncAttributeMaxDynamicSharedMemorySize, GEMM_SMEM);
    cudaFuncSetAttribute(gemm_cp<true, false>,
                         cudaFuncAttributeMaxDynamicSharedMemorySize, GEMM_SMEM);
    cudaFuncSetAttribute(attn_tc,
                         cudaFuncAttributeMaxDynamicSharedMemorySize, ATTN_SMEM);

    // One-shot tf32 conversion of all GEMM inputs (x, Wq‖Wk‖Wv, Wp)
    conv_tf<<<6272, 256>>>(x, Wk, Wv, Wq, Wp, xt, wqkvt, wpt);
    // Fused qkv projection: [4096,1152]; epilogue emits tf32 bits (q pre-scaled 0.125)
    gemm_cp<false, true><<<dim3(9, 32), 256, GEMM_SMEM>>>((const uint32_t*)xt,
                                                          (const uint32_t*)wqkvt, nullptr,
                                                          qkvb, NQKV, 1024);
    // attention -> y (tf32 bits, head-transposed layout baked in)
    attn_tc<<<512, 256, ATTN_SMEM>>>((const uint32_t*)qkvb, (uint32_t*)yb);
    // out = y @ Wp.T + bp (fp32 output)
    gemm_cp<true, false><<<dim3(8, 32), 256, GEMM_SMEM>>>((const uint32_t*)yb,
                                                          (const uint32_t*)wpt, bp, out,
                                                          1024, 1024);
}